// round 9
// baseline (speedup 1.0000x reference)
#include <cuda_runtime.h>
#include <cuda_bf16.h>
#include <cuda_fp16.h>
#include <math.h>
#include <stdint.h>

#define BB 4
#define SS 1024
#define DD 1024
#define HH 16
#define HD 64

typedef unsigned short ushort_t;

#define NACT (BB*SS*DD)           // 4M elements per activation plane

__device__ __half   g_Pf[(size_t)BB*HH*SS*SS];    // probs fp16 (128MB)
__device__ __half   g_Qf[BB*HH*SS*HD];
__device__ __half   g_Kf[BB*HH*SS*HD];
__device__ __half   g_Vf[BB*HH*SS*HD];
__device__ ushort_t g_Xhi[NACT], g_Xlo[NACT];     // X fp16 hi/lo planes
__device__ ushort_t g_Ahi[3*NACT], g_Alo[3*NACT]; // q/k/v activation fp16 hi/lo
__device__ ushort_t g_Bf [4*DD*DD];               // W^T fp16: q,k,v,o planes

// ---------------- helpers ----------------
__device__ __forceinline__ uint32_t smem_to_u32(const void* p) {
    uint32_t a;
    asm("{ .reg .u64 t; cvta.to.shared.u64 t, %1; cvt.u32.u64 %0, t; }"
        : "=r"(a) : "l"(p));
    return a;
}
__device__ __forceinline__ void cpa16(uint32_t s, const void* g) {
    asm volatile("cp.async.cg.shared.global [%0], [%1], 16;" :: "r"(s), "l"(g));
}
#define CP_COMMIT() asm volatile("cp.async.commit_group;")
#define CP_WAIT(n)  asm volatile("cp.async.wait_group %0;" :: "n"(n))

__device__ __forceinline__ void ldsm4(uint32_t* r, uint32_t addr) {
    asm volatile("ldmatrix.sync.aligned.m8n8.x4.shared.b16 {%0,%1,%2,%3}, [%4];"
        : "=r"(r[0]), "=r"(r[1]), "=r"(r[2]), "=r"(r[3]) : "r"(addr));
}
__device__ __forceinline__ void ldsm4t(uint32_t* r, uint32_t addr) {
    asm volatile("ldmatrix.sync.aligned.m8n8.x4.trans.shared.b16 {%0,%1,%2,%3}, [%4];"
        : "=r"(r[0]), "=r"(r[1]), "=r"(r[2]), "=r"(r[3]) : "r"(addr));
}
__device__ __forceinline__ void mma16816h(float* c, const uint32_t* a,
                                          uint32_t b0, uint32_t b1) {
    asm volatile(
        "mma.sync.aligned.m16n8k16.row.col.f32.f16.f16.f32 "
        "{%0,%1,%2,%3}, {%4,%5,%6,%7}, {%8,%9}, {%0,%1,%2,%3};"
        : "+f"(c[0]), "+f"(c[1]), "+f"(c[2]), "+f"(c[3])
        : "r"(a[0]), "r"(a[1]), "r"(a[2]), "r"(a[3]), "r"(b0), "r"(b1));
}
__device__ __forceinline__ void split1h(float v, ushort_t& h, ushort_t& l) {
    __half hb = __float2half_rn(v);
    float r = v - __half2float(hb);
    __half lb = __float2half_rn(r);
    h = __half_as_ushort(hb);
    l = __half_as_ushort(lb);
}

// ---------------- splits (merged launches) ----------------
__global__ __launch_bounds__(256) void split_act3(
    const float4* __restrict__ x0, const float4* __restrict__ x1,
    const float4* __restrict__ x2)
{
    const int z = blockIdx.y;
    const float4* x = (z == 0) ? x0 : (z == 1) ? x1 : x2;
    uint2* hi = reinterpret_cast<uint2*>(g_Ahi) + (size_t)z * (NACT/4);
    uint2* lo = reinterpret_cast<uint2*>(g_Alo) + (size_t)z * (NACT/4);
    int i = blockIdx.x * blockDim.x + threadIdx.x;
    float4 v = x[i];
    ushort_t h0,h1,h2,h3,l0,l1,l2,l3;
    split1h(v.x,h0,l0); split1h(v.y,h1,l1); split1h(v.z,h2,l2); split1h(v.w,h3,l3);
    hi[i] = make_uint2((uint32_t)h0 | ((uint32_t)h1 << 16),
                       (uint32_t)h2 | ((uint32_t)h3 << 16));
    lo[i] = make_uint2((uint32_t)l0 | ((uint32_t)l1 << 16),
                       (uint32_t)l2 | ((uint32_t)l3 << 16));
}

__global__ __launch_bounds__(256) void split_wT4(
    const float* __restrict__ W0, const float* __restrict__ W1,
    const float* __restrict__ W2, const float* __restrict__ W3)
{
    const int z = blockIdx.z;
    const float* W = (z == 0) ? W0 : (z == 1) ? W1 : (z == 2) ? W2 : W3;
    ushort_t* bf = g_Bf + (size_t)z * DD * DD;
    __shared__ float t[32][33];
    int n0 = blockIdx.x * 32, k0 = blockIdx.y * 32;
    int tx = threadIdx.x & 31, ty = threadIdx.x >> 5;
    #pragma unroll
    for (int j = 0; j < 4; j++)
        t[ty + 8*j][tx] = W[(size_t)(k0 + ty + 8*j) * DD + n0 + tx];
    __syncthreads();
    #pragma unroll
    for (int j = 0; j < 4; j++) {
        float v = t[tx][ty + 8*j];
        bf[(size_t)(n0 + ty + 8*j) * DD + k0 + tx]
            = __half_as_ushort(__float2half_rn(v));
    }
}

// ---------------- projection GEMM (fp16 split-2) ----------------
#define PJ_TILE  10240
#define PJ_STAGE (3*PJ_TILE)
#define PJ_SMEM  (2*PJ_STAGE)

__device__ __forceinline__ void proj_core(
    const ushort_t* __restrict__ Ahi, const ushort_t* __restrict__ Alo,
    const ushort_t* __restrict__ Bf, const float* __restrict__ bias,
    __half* __restrict__ Cf, float* __restrict__ Cext,
    char* smem, int m0, int n0)
{
    const uint32_t sb = smem_to_u32(smem);
    const int tid = threadIdx.x, lane = tid & 31, wid = tid >> 5;
    const int wm = wid >> 1, wn = wid & 1;

    const ushort_t* gsrc[3] = {Ahi, Alo, Bf};

    auto issue = [&](int stage, int k0) {
        #pragma unroll
        for (int i = 0; i < 6; i++) {
            int cid = i * 256 + tid;
            int t = cid >> 9;
            int idx = cid & 511;
            int r = idx >> 2, c = idx & 3;
            int grow = (t < 2 ? m0 : n0) + r;
            const ushort_t* g = gsrc[t] + (size_t)grow * 1024 + k0 + c * 8;
            cpa16(sb + stage * PJ_STAGE + t * PJ_TILE + r * 80 + c * 16, g);
        }
        CP_COMMIT();
    };

    float acc[2][8][4];
    #pragma unroll
    for (int i = 0; i < 2; i++)
        #pragma unroll
        for (int j = 0; j < 8; j++)
            #pragma unroll
            for (int c = 0; c < 4; c++) acc[i][j][c] = 0.f;

    issue(0, 0);
    for (int kc = 0; kc < 32; kc++) {
        if (kc < 31) { issue((kc + 1) & 1, (kc + 1) * 32); CP_WAIT(1); }
        else CP_WAIT(0);
        __syncthreads();
        const uint32_t s0  = sb + (kc & 1) * PJ_STAGE;
        const uint32_t sAh = s0, sAl = s0 + PJ_TILE, sB = s0 + 2*PJ_TILE;

        #pragma unroll
        for (int ks = 0; ks < 2; ks++) {
            uint32_t ah[2][4], al[2][4];
            #pragma unroll
            for (int i = 0; i < 2; i++) {
                uint32_t off = (uint32_t)(wm*32 + i*16 + (lane & 15)) * 80
                             + ((lane >> 4) * 16) + ks * 32;
                ldsm4(ah[i], sAh + off);
                ldsm4(al[i], sAl + off);
            }
            uint32_t b4[4][4];
            #pragma unroll
            for (int j4 = 0; j4 < 4; j4++) {
                uint32_t row = (uint32_t)(wn*64 + j4*16 + (lane & 7) + ((lane & 16) >> 1));
                uint32_t off = row * 80 + ks * 32 + ((lane & 8) << 1);
                ldsm4(b4[j4], sB + off);
            }
            #pragma unroll
            for (int i = 0; i < 2; i++)
                #pragma unroll
                for (int j = 0; j < 8; j++) {
                    int j4 = j >> 1, hh = (j & 1) * 2;
                    mma16816h(acc[i][j], ah[i], b4[j4][hh], b4[j4][hh+1]);
                    mma16816h(acc[i][j], al[i], b4[j4][hh], b4[j4][hh+1]);
                }
        }
        __syncthreads();
    }

    #pragma unroll
    for (int i = 0; i < 2; i++) {
        int mlo = m0 + wm*32 + i*16 + (lane >> 2);
        #pragma unroll
        for (int half = 0; half < 2; half++) {
            int m = mlo + half * 8;
            int b = m >> 10, s = m & 1023;
            #pragma unroll
            for (int j = 0; j < 8; j++) {
                int col = n0 + wn*64 + j*8 + 2*(lane & 3);
                float v0 = acc[i][j][half*2 + 0] + bias[col];
                float v1 = acc[i][j][half*2 + 1] + bias[col + 1];
                if (Cext) {
                    *reinterpret_cast<float2*>(Cext + (size_t)m * 1024 + col)
                        = make_float2(v0, v1);
                } else {
                    int h = col >> 6, hd = col & 63;
                    size_t o = ((size_t)((b << 4) + h) * 1024 + s) * 64 + hd;
                    *reinterpret_cast<__half2*>(Cf + o) = __floats2half2_rn(v0, v1);
                }
            }
        }
    }
}

__global__ __launch_bounds__(256) void proj_qkv(
    const float* __restrict__ b0, const float* __restrict__ b1,
    const float* __restrict__ b2)
{
    extern __shared__ char smem[];
    const int z = blockIdx.z;
    const ushort_t* Ahi = g_Ahi + (size_t)z * NACT;
    const ushort_t* Alo = g_Alo + (size_t)z * NACT;
    const ushort_t* Bf  = g_Bf  + (size_t)z * DD * DD;
    const float* bias = (z == 0) ? b0 : (z == 1) ? b1 : b2;
    __half* Cf = (z == 0) ? g_Qf : (z == 1) ? g_Kf : g_Vf;
    proj_core(Ahi, Alo, Bf, bias, Cf, nullptr, smem,
              blockIdx.y * 128, blockIdx.x * 128);
}

__global__ __launch_bounds__(256) void proj_out(
    const float* __restrict__ bias, float* __restrict__ Cext)
{
    extern __shared__ char smem[];
    proj_core(g_Xhi, g_Xlo, g_Bf + (size_t)3 * DD * DD, bias, nullptr, Cext,
              smem, blockIdx.y * 128, blockIdx.x * 128);
}

// ---------------- fused scores + softmax -> Pf (fp16) ----------------
// CTA: (bh, 32 q-rows) x all 1024 keys. Block 512 = 16 warps:
// wm = row-half (16 rows), wn = col group; warp covers cols {c*128 + wn*16}.
// K streamed in 8 chunks of 128 rows, cp.async double-buffered.
#define KCH      18432                 // 128 rows * 144 B
#define SC2_K0   0                     // 2 chunks  -> 36864
#define SC2_Q    36864                 // 32 * 144  ->  4608
#define SC2_ST   41472                 // 32 * 2064 -> 66048
#define SC2_RM   107520                // 32*8 floats -> 1024
#define SC2_RS   108544                // 32*8 floats -> 1024
#define SC2_SMEM 109568

__global__ __launch_bounds__(512) void scsm()
{
    extern __shared__ char smem[];
    const uint32_t sb = smem_to_u32(smem);
    const int tid = threadIdx.x, lane = tid & 31, w = tid >> 5;
    const int wm = w >> 3, wn = w & 7;
    const int bh = blockIdx.y;
    const int q0 = blockIdx.x * 32;

    const __half* Qp = g_Qf + (size_t)bh * SS * HD;
    const __half* Kp = g_Kf + (size_t)bh * SS * HD;

    // Q (32x64) staged once; grouped with chunk 0
    if (tid < 256) {
        int r = tid >> 3, u = tid & 7;
        cpa16(sb + SC2_Q + r * 144 + u * 16, Qp + (size_t)(q0 + r) * 64 + u * 8);
    }
    auto loadK = [&](int stage, int c) {
        #pragma unroll
        for (int i = 0; i < 2; i++) {
            int cid = i * 512 + tid;
            int r = cid >> 3, u = cid & 7;
            cpa16(sb + SC2_K0 + stage * KCH + r * 144 + u * 16,
                  Kp + (size_t)(c * 128 + r) * 64 + u * 8);
        }
        CP_COMMIT();
    };

    float acc[8][2][4];
    #pragma unroll
    for (int j = 0; j < 8; j++)
        #pragma unroll
        for (int t = 0; t < 2; t++)
            #pragma unroll
            for (int c = 0; c < 4; c++) acc[j][t][c] = 0.f;

    uint32_t afr[4][4];

    loadK(0, 0);
    for (int c = 0; c < 8; c++) {
        if (c < 7) { loadK((c + 1) & 1, c + 1); CP_WAIT(1); }
        else CP_WAIT(0);
        __syncthreads();
        if (c == 0) {
            #pragma unroll
            for (int ks = 0; ks < 4; ks++) {
                uint32_t off = (uint32_t)(wm*16 + (lane & 15)) * 144
                             + ks * 32 + ((lane >> 4) * 16);
                ldsm4(afr[ks], sb + SC2_Q + off);
            }
        }
        const uint32_t base = sb + SC2_K0 + (c & 1) * KCH;
        const uint32_t row = (uint32_t)(wn*16 + (lane & 7) + ((lane & 16) >> 1));
        #pragma unroll
        for (int ks = 0; ks < 4; ks++) {
            uint32_t b4[4];
            ldsm4(b4, base + row * 144 + ks * 32 + ((lane & 8) << 1));
            mma16816h(acc[c][0], afr[ks], b4[0], b4[1]);
            mma16816h(acc[c][1], afr[ks], b4[2], b4[3]);
        }
        __syncthreads();
    }

    // rows handled by this thread (local 0..31)
    const int r1 = wm * 16 + (lane >> 2);
    const int r2 = r1 + 8;

    // ---- row max ----
    float m1 = -1e30f, m2 = -1e30f;
    #pragma unroll
    for (int j = 0; j < 8; j++)
        #pragma unroll
        for (int t = 0; t < 2; t++) {
            m1 = fmaxf(m1, fmaxf(acc[j][t][0], acc[j][t][1]));
            m2 = fmaxf(m2, fmaxf(acc[j][t][2], acc[j][t][3]));
        }
    #pragma unroll
    for (int o = 1; o <= 2; o <<= 1) {
        m1 = fmaxf(m1, __shfl_xor_sync(0xffffffffu, m1, o));
        m2 = fmaxf(m2, __shfl_xor_sync(0xffffffffu, m2, o));
    }
    float* redm = reinterpret_cast<float*>(smem + SC2_RM);
    if ((lane & 3) == 0) { redm[r1*8 + wn] = m1; redm[r2*8 + wn] = m2; }
    __syncthreads();
    float M1 = redm[r1*8], M2 = redm[r2*8];
    #pragma unroll
    for (int i = 1; i < 8; i++) {
        M1 = fmaxf(M1, redm[r1*8 + i]);
        M2 = fmaxf(M2, redm[r2*8 + i]);
    }

    // ---- exp + row sum (scale 0.125 applied inside exp) ----
    float s1 = 0.f, s2 = 0.f;
    #pragma unroll
    for (int j = 0; j < 8; j++)
        #pragma unroll
        for (int t = 0; t < 2; t++) {
            acc[j][t][0] = expf((acc[j][t][0] - M1) * 0.125f);
            acc[j][t][1] = expf((acc[j][t][1] - M1) * 0.125f);
            acc[j][t][2] = expf((acc[j][t][2] - M2) * 0.125f);
            acc[j][t][3] = expf((acc[j][t][3] - M2) * 0.125f);
            s1 += acc[j][t][0] + acc[j][t][1];
            s2 += acc[j][t][2] + acc[j][t][3];
        }
    #pragma unroll
    for (int o = 1; o <= 2; o <<= 1) {
        s1 += __shfl_xor_sync(0xffffffffu, s1, o);
        s2 += __shfl_xor_sync(0xffffffffu, s2, o);
    }
    float* reds = reinterpret_cast<float*>(smem + SC2_RS);
    if ((lane & 3) == 0) { reds[r1*8 + wn] = s1; reds[r2*8 + wn] = s2; }
    __syncthreads();
    float S1 = 0.f, S2 = 0.f;
    #pragma unroll
    for (int i = 0; i < 8; i++) { S1 += reds[r1*8 + i]; S2 += reds[r2*8 + i]; }
    const float inv1 = 1.f / S1, inv2 = 1.f / S2;

    // ---- stage p as fp16 (conflict-free), then coalesced copy-out ----
    #pragma unroll
    for (int j = 0; j < 8; j++)
        #pragma unroll
        for (int t = 0; t < 2; t++) {
            int col = j*128 + wn*16 + t*8 + (lane & 3)*2;
            __half2 h1 = __floats2half2_rn(acc[j][t][0]*inv1, acc[j][t][1]*inv1);
            __half2 h2 = __floats2half2_rn(acc[j][t][2]*inv2, acc[j][t][3]*inv2);
            *reinterpret_cast<__half2*>(smem + SC2_ST + r1*2064 + col*2) = h1;
            *reinterpret_cast<__half2*>(smem + SC2_ST + r2*2064 + col*2) = h2;
        }
    __syncthreads();

    __half* Pout = g_Pf + (size_t)bh * SS * SS;
    #pragma unroll
    for (int rr = 0; rr < 2; rr++) {
        int row = w * 2 + rr;
        __half* grow = Pout + (size_t)(q0 + row) * SS;
        #pragma unroll
        for (int i = 0; i < 4; i++) {
            uint4 v = *reinterpret_cast<uint4*>(smem + SC2_ST + row*2064 + i*512 + lane*16);
            *reinterpret_cast<uint4*>(grow + i*256 + lane*8) = v;
        }
    }
}

// ---------------- attn_c from Pf ----------------
__global__ __launch_bounds__(256) void attnc(
    const float* __restrict__ Wc, const float* __restrict__ bcp,
    float* __restrict__ attn_out)
{
    const int b = blockIdx.x >> 10;
    const int q = blockIdx.x & 1023;
    const int t = threadIdx.x;

    float a0 = 0.f, a1 = 0.f, a2 = 0.f, a3 = 0.f;
    #pragma unroll
    for (int h = 0; h < HH; h++) {
        const uint2 v = *reinterpret_cast<const uint2*>(
            g_Pf + ((size_t)((b << 4) + h) * SS + q) * SS + t * 4);
        float2 p01 = __half22float2(*reinterpret_cast<const __half2*>(&v.x));
        float2 p23 = __half22float2(*reinterpret_cast<const __half2*>(&v.y));
        float w = Wc[h];
        a0 = fmaf(w, p01.x, a0); a1 = fmaf(w, p01.y, a1);
        a2 = fmaf(w, p23.x, a2); a3 = fmaf(w, p23.y, a3);
    }
    const float bcv = bcp[0];
    *reinterpret_cast<float4*>(attn_out + ((size_t)b * SS + q) * SS + t * 4)
        = make_float4(a0 + bcv, a1 + bcv, a2 + bcv, a3 + bcv);
}

// ---------------- PV (single fp16 MMA; X out fp16 hi/lo) ----------------
#define PV_PTILE 10240            // 128*40*2
#define PV_VTILE 4608             // 32*72*2
#define PV_STAGE (PV_PTILE + PV_VTILE)   // 14848
#define PV_SMEM  (2*PV_STAGE)

__global__ __launch_bounds__(256) void pv_mma()
{
    extern __shared__ char smem[];
    const uint32_t sb = smem_to_u32(smem);
    const int tid = threadIdx.x, lane = tid & 31, wid = tid >> 5;
    const int wm = wid >> 1, wn = wid & 1;
    const int bh = blockIdx.y;
    const int m0 = blockIdx.x * 128;
    const int b = bh >> 4, h = bh & 15;

    auto issue = [&](int stage, int k0) {
        uint32_t s0 = sb + stage * PV_STAGE;
        #pragma unroll
        for (int i = 0; i < 3; i++) {
            int cid = i * 256 + tid;
            if (cid < 512) {
                int r = cid >> 2, c = cid & 3;
                const __half* g = g_Pf
                    + ((size_t)bh * 1024 + m0 + r) * 1024 + k0 + c * 8;
                cpa16(s0 + r * 80 + c * 16, g);
            } else {
                int idx = cid - 512;
                int r = idx >> 3, c = idx & 7;
                const __half* g = g_Vf
                    + ((size_t)bh * 1024 + k0 + r) * 64 + c * 8;
                cpa16(s0 + PV_PTILE + r * 144 + c * 16, g);
            }
        }
        CP_COMMIT();
    };

    float acc[2][4][4];
    #pragma unroll
    for (int i = 0; i < 2; i++)
        #pragma unroll
        for (int j = 0; j < 4; j++)
            #pragma unroll
            for (int c = 0; c < 4; c++) acc[i][j][c] = 0.f;

    issue(0, 0);
    for (int kc = 0; kc < 32; kc++) {
        if (kc < 31) { issue((kc + 1) & 1, (kc + 1) * 32); CP_WAIT(1); }
        else CP_WAIT(0);
        __syncthreads();
        const uint32_t s0 = sb + (kc & 1) * PV_STAGE;
        const uint32_t sP = s0, sV = s0 + PV_PTILE;

        #pragma unroll
        for (int ks = 0; ks < 2; ks++) {
            uint32_t a[2][4];
            #pragma unroll
            for (int i = 0; i < 2; i++) {
                uint32_t off = (uint32_t)(wm*32 + i*16 + (lane & 15)) * 80
                             + ((lane >> 4) * 16) + ks * 32;
                ldsm4(a[i], sP + off);
            }
            uint32_t b2[2][4];
            #pragma unroll
            for (int j2 = 0; j2 < 2; j2++) {
                uint32_t row = (uint32_t)(ks*16 + (lane & 7) + ((lane & 8) ? 8 : 0));
                uint32_t col = (uint32_t)(wn*32 + j2*16 + ((lane & 16) ? 8 : 0));
                ldsm4t(b2[j2], sV + row * 144 + col * 2);
            }
            #pragma unroll
            for (int i = 0; i < 2; i++)
                #pragma unroll
                for (int j = 0; j < 4; j++) {
                    int j2 = j >> 1, hh = (j & 1) * 2;
                    mma16816h(acc[i][j], a[i], b2[j2][hh], b2[j2][hh+1]);
                }
        }
        __syncthreads();
    }

    #pragma unroll
    for (int i = 0; i < 2; i++) {
        int qlo = m0 + wm*32 + i*16 + (lane >> 2);
        #pragma unroll
        for (int half = 0; half < 2; half++) {
            int q = qlo + half * 8;
            #pragma unroll
            for (int j = 0; j < 4; j++) {
                int hd = wn*32 + j*8 + 2*(lane & 3);
                float v0 = acc[i][j][half*2 + 0];
                float v1 = acc[i][j][half*2 + 1];
                size_t o = ((size_t)(b * 1024 + q)) * 1024 + h * 64 + hd;
                ushort_t h0,l0,h1,l1;
                split1h(v0, h0, l0); split1h(v1, h1, l1);
                *reinterpret_cast<ushort2*>(g_Xhi + o) = make_ushort2(h0, h1);
                *reinterpret_cast<ushort2*>(g_Xlo + o) = make_ushort2(l0, l1);
            }
        }
    }
}

// ---------------------------------------------------------------------------
extern "C" void kernel_launch(void* const* d_in, const int* in_sizes, int n_in,
                              void* d_out, int out_size)
{
    (void)in_sizes; (void)n_in; (void)out_size;
    const float* query = (const float*)d_in[0];
    const float* key   = (const float*)d_in[1];
    const float* value = (const float*)d_in[2];
    const float* Wq = (const float*)d_in[3];  const float* bq = (const float*)d_in[4];
    const float* Wk = (const float*)d_in[5];  const float* bk = (const float*)d_in[6];
    const float* Wv = (const float*)d_in[7];  const float* bv = (const float*)d_in[8];
    const float* Wo = (const float*)d_in[9];  const float* bo = (const float*)d_in[10];
    const float* Wc = (const float*)d_in[11]; const float* bc = (const float*)d_in[12];

    float* out = (float*)d_out;
    float* attn_out = out + (size_t)BB * SS * DD;

    static bool attr_done = false;
    if (!attr_done) {
        cudaFuncSetAttribute(proj_qkv, cudaFuncAttributeMaxDynamicSharedMemorySize, PJ_SMEM);
        cudaFuncSetAttribute(proj_out, cudaFuncAttributeMaxDynamicSharedMemorySize, PJ_SMEM);
        cudaFuncSetAttribute(scsm,     cudaFuncAttributeMaxDynamicSharedMemorySize, SC2_SMEM);
        cudaFuncSetAttribute(pv_mma,   cudaFuncAttributeMaxDynamicSharedMemorySize, PV_SMEM);
        attr_done = true;
    }

    const int NACT4 = NACT / 4;

    split_act3<<<dim3(NACT4/256, 3), 256>>>(
        (const float4*)query, (const float4*)key, (const float4*)value);
    split_wT4<<<dim3(32, 32, 4), 256>>>(Wq, Wk, Wv, Wo);

    proj_qkv<<<dim3(8, 32, 3), 256, PJ_SMEM>>>(bq, bk, bv);

    // fused scores + softmax -> Pf
    scsm<<<dim3(32, BB*HH), 512, SC2_SMEM>>>();

    attnc<<<BB * SS, 256>>>(Wc, bc, attn_out);
    pv_mma<<<dim3(8, BB*HH), 256, PV_SMEM>>>();

    proj_out<<<dim3(8, 32), 256, PJ_SMEM>>>(bo, out);
}